// round 12
// baseline (speedup 1.0000x reference)
#include <cuda_runtime.h>
#include <cstddef>

// Wave FDTD scan, register-resident version.
// y_t = w*(up+dn+lf+rg) + d*y_{t-1} + e*y_{t-2}, source at (96,32).
// One 8-CTA cluster per batch; CTA owns 24 rows x 192 cols.
// 192 threads/CTA; each thread owns a 2-col x 12-row register tile.
// Horizontal neighbors via warp shuffle; vertical via register roll;
// warp-edge columns + hf-boundary rows via SMEM; CTA-boundary rows via DSMEM.

#define NXg 192
#define NYg 192
#define Tg  256
#define CLUSTER 8
#define ROWS_PER 24
#define ROWS_T 12
#define CPT 96            // column pairs per row
#define THREADS 192

typedef unsigned long long ull;

// ---- packed f32x2 math (Blackwell) ----
__device__ __forceinline__ ull f2add(ull a, ull b) {
    ull r; asm("add.rn.f32x2 %0,%1,%2;" : "=l"(r) : "l"(a), "l"(b)); return r;
}
__device__ __forceinline__ ull f2mul(ull a, ull b) {
    ull r; asm("mul.rn.f32x2 %0,%1,%2;" : "=l"(r) : "l"(a), "l"(b)); return r;
}
__device__ __forceinline__ ull f2fma(ull a, ull b, ull c) {
    ull r; asm("fma.rn.f32x2 %0,%1,%2,%3;" : "=l"(r) : "l"(a), "l"(b), "l"(c)); return r;
}
__device__ __forceinline__ ull pack2(float lo, float hi) {
    ull r; asm("mov.b64 %0,{%1,%2};" : "=l"(r) : "f"(lo), "f"(hi)); return r;
}
__device__ __forceinline__ void unpack2(ull v, float& lo, float& hi) {
    asm("mov.b64 {%0,%1},%2;" : "=f"(lo), "=f"(hi) : "l"(v));
}

// ---- cluster helpers ----
__device__ __forceinline__ unsigned mapa_u32(unsigned addr, unsigned rank) {
    unsigned ret;
    asm volatile("mapa.shared::cluster.u32 %0, %1, %2;" : "=r"(ret) : "r"(addr), "r"(rank));
    return ret;
}
__device__ __forceinline__ void st_cluster_u64(unsigned addr, ull v) {
    asm volatile("st.shared::cluster.b64 [%0], %1;" :: "r"(addr), "l"(v) : "memory");
}
__device__ __forceinline__ void cluster_sync_() {
    asm volatile("barrier.cluster.arrive.aligned;" ::: "memory");
    asm volatile("barrier.cluster.wait.aligned;"   ::: "memory");
}

__global__ void __launch_bounds__(THREADS, 1) __cluster_dims__(CLUSTER, 1, 1)
wave_scan_kernel(const float* __restrict__ xin,   // [B, T]
                 const float* __restrict__ cin,   // [192,192]
                 const float* __restrict__ bin,   // [192,192]
                 float* __restrict__ out)         // [B, T, 192, 192]
{
    // Double-buffered exchange buffers (slot = step parity).
    __shared__ ull dsTop[2][CPT];   // row (r0_cta - 1), pushed by upper neighbor
    __shared__ ull dsBot[2][CPT];   // row (r0_cta + 24), pushed by lower neighbor
    __shared__ ull mid11[2][CPT];   // strip row 11 (hf0's y1[11]) -> hf1's ym at r=0
    __shared__ ull mid12[2][CPT];   // strip row 12 (hf1's y1[0])  -> hf0's yp at r=11
    __shared__ float ebR[2][2][2][ROWS_T]; // right-edge col of warp w (w=0,1), read by warp w+1 lane0
    __shared__ float ebL[2][2][3][ROWS_T]; // left-edge col of warp w (w=1,2), read by warp w-1 lane31
    __shared__ float xs[Tg];

    const int tid   = threadIdx.x;
    const int lane  = tid & 31;
    const int cp    = tid % CPT;        // column pair 0..95 (cols 2cp, 2cp+1)
    const int hf    = tid / CPT;        // row half 0/1
    const int wInHf = cp >> 5;          // warp index within half: 0,1,2
    const int rk    = blockIdx.x;       // strip index (cluster rank)
    const int bt    = blockIdx.y;       // batch

    // Zero all exchange buffers (both slots) — boundary halos stay zero forever.
    if (tid < CPT) {
        dsTop[0][tid] = 0; dsTop[1][tid] = 0;
        dsBot[0][tid] = 0; dsBot[1][tid] = 0;
        mid11[0][tid] = 0; mid11[1][tid] = 0;
        mid12[0][tid] = 0; mid12[1][tid] = 0;
    }
    {
        float* eb = (float*)ebR;                       // 96 + 144 contiguous? not guaranteed;
        for (int i = tid; i < 2*2*2*ROWS_T; i += THREADS) eb[i] = 0.0f;
        float* el = (float*)ebL;
        for (int i = tid; i < 2*2*3*ROWS_T; i += THREADS) el[i] = 0.0f;
    }
    for (int i = tid; i < Tg; i += THREADS) xs[i] = xin[bt * Tg + i];

    // Constants
    const float dtv     = 1e-3f;
    const float inv_dt2 = 1.0f / (dtv * dtv);
    const float Hv      = dtv * 1.4142135623730951f * 1.01f;
    const float inv_h2  = 1.0f / (Hv * Hv);

    const int r0 = rk * ROWS_PER + hf * ROWS_T;   // first global row of this thread

    // Per-cell coefficients (packed), field registers.
    ull wv[ROWS_T], dv[ROWS_T], ev[ROWS_T], y1[ROWS_T], y2[ROWS_T];
#pragma unroll
    for (int r = 0; r < ROWS_T; r++) {
        const int gi = (r0 + r) * NYg + 2 * cp;
        const float2 c2 = *(const float2*)(cin + gi);
        const float2 b2 = *(const float2*)(bin + gi);
        float wq[2], dq[2], eq[2];
        {
            const float hb = 0.5f * b2.x / dtv;
            const float ai = 1.0f / (inv_dt2 + hb);
            wq[0] = ai * c2.x * c2.x * inv_h2;
            dq[0] = 2.0f * inv_dt2 * ai - 4.0f * wq[0];
            eq[0] = -(inv_dt2 - hb) * ai;
        }
        {
            const float hb = 0.5f * b2.y / dtv;
            const float ai = 1.0f / (inv_dt2 + hb);
            wq[1] = ai * c2.y * c2.y * inv_h2;
            dq[1] = 2.0f * inv_dt2 * ai - 4.0f * wq[1];
            eq[1] = -(inv_dt2 - hb) * ai;
        }
        wv[r] = pack2(wq[0], wq[1]);
        dv[r] = pack2(dq[0], dq[1]);
        ev[r] = pack2(eq[0], eq[1]);
        y1[r] = 0ull;
        y2[r] = 0ull;
    }

    const bool isSrc = (rk == 4) && (hf == 0) && (cp == 16);  // row 96, col 32 (.x lane)
    float* oBase = out + ((size_t)bt * Tg) * (NXg * NYg) + (size_t)r0 * NYg + 2 * cp;

    // DSMEM push targets (computed once).
    const bool pushUp = (hf == 0) && (rk > 0);
    const bool pushDn = (hf == 1) && (rk < CLUSTER - 1);
    unsigned upAddr = 0, dnAddr = 0, upAddr1 = 0, dnAddr1 = 0;
    if (pushUp) {
        upAddr  = mapa_u32((unsigned)__cvta_generic_to_shared(&dsBot[0][cp]), (unsigned)(rk - 1));
        upAddr1 = mapa_u32((unsigned)__cvta_generic_to_shared(&dsBot[1][cp]), (unsigned)(rk - 1));
    }
    if (pushDn) {
        dnAddr  = mapa_u32((unsigned)__cvta_generic_to_shared(&dsTop[0][cp]), (unsigned)(rk + 1));
        dnAddr1 = mapa_u32((unsigned)__cvta_generic_to_shared(&dsTop[1][cp]), (unsigned)(rk + 1));
    }

    cluster_sync_();   // zeros + xs visible cluster-wide

    for (int t = 0; t < Tg; t++) {
        const int s = (t + 1) & 1;   // read slot (holds y_{t-1} edges)
        const int w = t & 1;         // write slot (receives y_t edges)
        const ull srcAdd = pack2(isSrc ? xs[t] : 0.0f, 0.0f);

        const ull top = (hf == 0) ? dsTop[s][cp] : mid11[s][cp];
        const ull bot = (hf == 0) ? mid12[s][cp] : dsBot[s][cp];

        float* oT = oBase + (size_t)t * (NXg * NYg);
        ull up = top;

#pragma unroll
        for (int r = 0; r < ROWS_T; r++) {
            const ull cen = y1[r];
            const ull dn  = (r == ROWS_T - 1) ? bot : y1[r + 1];
            float lo, hi;
            unpack2(cen, lo, hi);

            float lfs = __shfl_up_sync(0xffffffffu, hi, 1);   // neighbor pair's .y = col 2cp-1
            float rgs = __shfl_down_sync(0xffffffffu, lo, 1); // neighbor pair's .x = col 2cp+2
            if (lane == 0)  lfs = (wInHf == 0) ? 0.0f : ebR[s][hf][wInHf - 1][r];
            if (lane == 31) rgs = (wInHf == 2) ? 0.0f : ebL[s][hf][wInHf + 1][r];

            const ull lfv = pack2(lfs, lo);   // left neighbors of (x, y)
            const ull rgv = pack2(hi, rgs);   // right neighbors of (x, y)

            const ull ssum = f2add(f2add(up, dn), f2add(lfv, rgv));
            ull yn = f2fma(wv[r], ssum, f2fma(dv[r], cen, f2mul(ev[r], y2[r])));
            if (r == 0) yn = f2add(yn, srcAdd);

            *(ull*)(oT + (size_t)r * NYg) = yn;  // STG.64, coalesced

            y2[r] = cen;
            y1[r] = yn;
            up = cen;
        }

        // --- publish new edges for step t+1 (slot w) ---
        if (lane == 31 && wInHf < 2) {
#pragma unroll
            for (int r = 0; r < ROWS_T; r++) {
                float lo, hi; unpack2(y1[r], lo, hi);
                ebR[w][hf][wInHf][r] = hi;
            }
        }
        if (lane == 0 && wInHf > 0) {
#pragma unroll
            for (int r = 0; r < ROWS_T; r++) {
                float lo, hi; unpack2(y1[r], lo, hi);
                ebL[w][hf][wInHf][r] = lo;
            }
        }
        if (hf == 0) mid11[w][cp] = y1[ROWS_T - 1];
        else         mid12[w][cp] = y1[0];

        if (pushUp) st_cluster_u64(w ? upAddr1 : upAddr, y1[0]);            // our row 0 -> upper.dsBot
        if (pushDn) st_cluster_u64(w ? dnAddr1 : dnAddr, y1[ROWS_T - 1]);   // our row 23 -> lower.dsTop

        cluster_sync_();  // release our writes (incl. DSMEM), acquire neighbors'
    }
}

extern "C" void kernel_launch(void* const* d_in, const int* in_sizes, int n_in,
                              void* d_out, int out_size) {
    const float* x = (const float*)d_in[0];   // [B, T, 1]
    const float* c = (const float*)d_in[1];   // [192, 192]
    const float* b = (const float*)d_in[2];   // [192, 192]
    float* out = (float*)d_out;               // [B, T, 192, 192]

    const int B = in_sizes[0] / Tg;           // 4
    dim3 grid(CLUSTER, B, 1);
    wave_scan_kernel<<<grid, THREADS>>>(x, c, b, out);
}